// round 1
// baseline (speedup 1.0000x reference)
#include <cuda_runtime.h>

// Problem constants (match reference)
#define LRATE  0.001f
#define GAMMA_ 0.99f
#define LEN_C  512
#define R_     4
#define S_     8
#define E_     8
#define T_     2048
#define RS_    (R_ * S_)            // 32
#define W_ELEMS (RS_ * LEN_C)       // 16384 floats = 64KB

// Scratch (allocation-free rule: __device__ globals)
__device__ float g_error[E_];
__device__ float g_W[W_ELEMS];

// ---------------------------------------------------------------------------
// Kernel A: error[e] = Dis[e, LEN_C-1] - sum_{rs,n} Fx[rs,e,n] * W0[rs,n]
// 8 blocks (one per e), 256 threads each. Tiny.
// ---------------------------------------------------------------------------
__global__ void k_error(const float* __restrict__ Fx,
                        const float* __restrict__ Dis,
                        const float* __restrict__ W0) {
    const int e   = blockIdx.x;
    const int tid = threadIdx.x;
    float acc = 0.0f;
    for (int i = tid; i < W_ELEMS; i += 256) {
        const int rs = i >> 9;        // i / 512
        const int n  = i & (LEN_C - 1);
        acc += Fx[(rs * E_ + e) * LEN_C + n] * W0[i];
    }
    __shared__ float s[256];
    s[tid] = acc;
    __syncthreads();
    #pragma unroll
    for (int off = 128; off > 0; off >>= 1) {
        if (tid < off) s[tid] += s[tid + off];
        __syncthreads();
    }
    if (tid == 0) g_error[e] = Dis[e * LEN_C + (LEN_C - 1)] - s[0];
}

// ---------------------------------------------------------------------------
// Kernel B: W[i] = W0[i] + LR * sum_e error[e] * Fx[rs,e,n]
//   (control_weights = W0 - 0.5*LR*(-2*grad) = W0 + LR*grad)
// Also writes gam_vector[i] = GAMMA^(LEN_C-1-i) into the output tail.
// ---------------------------------------------------------------------------
__global__ void k_weights(const float* __restrict__ Fx,
                          const float* __restrict__ W0,
                          float* __restrict__ gam_out) {
    const int i = blockIdx.x * blockDim.x + threadIdx.x;
    if (i < W_ELEMS) {
        const int rs = i >> 9;
        const int n  = i & (LEN_C - 1);
        float s = 0.0f;
        #pragma unroll
        for (int e = 0; e < E_; e++)
            s += g_error[e] * Fx[(rs * E_ + e) * LEN_C + n];
        g_W[i] = W0[i] + LRATE * s;
    }
    if (i < LEN_C) {
        gam_out[i] = powf(GAMMA_, (float)(LEN_C - 1 - i));
    }
}

// ---------------------------------------------------------------------------
// Kernel C (the 1 GiB streamer):
//   out[t,e] = sum_{rs,n} Fx_extend[t,rs,e,n] * W[rs,n]
// One CTA per t. W staged in 64KB dynamic smem. 512 threads, float4 loads.
//
// Flat float4 index v in [0, 32768): row = v/128 (rs*8+e), n4 = v%128.
// Thread tid, iteration it: v = it*512 + tid
//   row = it*4 + tid/128  -> e = row%8 alternates e0 (even it) / e0+4 (odd it)
//   rs  = row>>3, n4 = tid&127 (fixed per thread)
// ---------------------------------------------------------------------------
extern __shared__ float4 sW[];      // 4096 float4 = 64KB

__global__ __launch_bounds__(512) void k_main(const float* __restrict__ Fxe,
                                              float* __restrict__ out) {
    const int tid = threadIdx.x;
    const int t   = blockIdx.x;

    __shared__ float sAcc[E_];

    // Stage W into smem (coalesced float4, L2-resident across CTAs)
    const float4* W4 = reinterpret_cast<const float4*>(g_W);
    #pragma unroll
    for (int i = 0; i < 8; i++) sW[tid + i * 512] = W4[tid + i * 512];
    if (tid < E_) sAcc[tid] = 0.0f;
    __syncthreads();

    const float4* X = reinterpret_cast<const float4*>(Fxe) + (size_t)t * 32768;

    const int e0 = tid >> 7;     // 0..3
    const int n4 = tid & 127;

    float acc0 = 0.0f;           // accumulates e = e0      (even iterations)
    float acc1 = 0.0f;           // accumulates e = e0 + 4  (odd iterations)

    #pragma unroll 8
    for (int it = 0; it < 64; it++) {
        const int v   = it * 512 + tid;
        const int row = it * 4 + e0;
        const int rs  = row >> 3;
        const float4 x = X[v];
        const float4 w = sW[rs * 128 + n4];
        const float d = x.x * w.x + x.y * w.y + x.z * w.z + x.w * w.w;
        if (it & 1) acc1 += d; else acc0 += d;
    }

    // Warp reduce (all lanes of a warp share e0)
    #pragma unroll
    for (int off = 16; off > 0; off >>= 1) {
        acc0 += __shfl_xor_sync(0xFFFFFFFFu, acc0, off);
        acc1 += __shfl_xor_sync(0xFFFFFFFFu, acc1, off);
    }
    if ((tid & 31) == 0) {
        atomicAdd(&sAcc[e0],     acc0);
        atomicAdd(&sAcc[e0 + 4], acc1);
    }
    __syncthreads();
    if (tid < E_) out[t * E_ + tid] = sAcc[tid];
}

// ---------------------------------------------------------------------------
extern "C" void kernel_launch(void* const* d_in, const int* in_sizes, int n_in,
                              void* d_out, int out_size) {
    const float* Fx  = (const float*)d_in[0];   // [R,S,E,LEN_C]
    const float* Dis = (const float*)d_in[1];   // [E,LEN_C]
    const float* Fxe = (const float*)d_in[2];   // [T,R,S,E,LEN_C]
    const float* W0  = (const float*)d_in[3];   // [R,S,LEN_C]
    float* out = (float*)d_out;                 // [T*E] anti_noise ++ [LEN_C] gamma

    k_error<<<E_, 256>>>(Fx, Dis, W0);
    k_weights<<<(W_ELEMS + 255) / 256, 256>>>(Fx, W0, out + (size_t)T_ * E_);

    static bool attr_set = false;
    if (!attr_set) {
        cudaFuncSetAttribute(k_main, cudaFuncAttributeMaxDynamicSharedMemorySize, 65536);
        attr_set = true;
    }
    k_main<<<T_, 512, 65536>>>(Fxe, out);
}

// round 2
// speedup vs baseline: 1.0321x; 1.0321x over previous
#include <cuda_runtime.h>

// Problem constants (match reference)
#define LRATE  0.001f
#define GAMMA_ 0.99f
#define LEN_C  512
#define R_     4
#define S_     8
#define E_     8
#define T_     2048
#define RS_    (R_ * S_)            // 32
#define W_ELEMS (RS_ * LEN_C)       // 16384 floats = 64KB

// Scratch (allocation-free rule: __device__ globals)
__device__ float g_partial[RS_ * E_];   // per-(rs,e) partial dot products
__device__ float g_W[W_ELEMS];          // updated control weights

// ---------------------------------------------------------------------------
// Kernel A: g_partial[rs,e] = sum_n Fx[rs,e,n] * W0[rs,n]
// 32 blocks (one per rs), 256 threads = 8 warps (one warp per e).
// Per block: 16KB Fx + 2KB W0 — pure latency, ~2-3us total.
// ---------------------------------------------------------------------------
__global__ __launch_bounds__(256) void k_error_partial(
        const float* __restrict__ Fx,
        const float* __restrict__ W0) {
    const int rs   = blockIdx.x;
    const int e    = threadIdx.x >> 5;      // warp id = e
    const int lane = threadIdx.x & 31;

    const float4* Fx4 = reinterpret_cast<const float4*>(Fx) + (rs * E_ + e) * 128;
    const float4* W4  = reinterpret_cast<const float4*>(W0) + rs * 128;

    float acc = 0.0f;
    #pragma unroll
    for (int i = 0; i < 4; i++) {
        const float4 x = Fx4[lane + 32 * i];
        const float4 w = W4 [lane + 32 * i];
        acc += x.x * w.x + x.y * w.y + x.z * w.z + x.w * w.w;
    }
    #pragma unroll
    for (int off = 16; off > 0; off >>= 1)
        acc += __shfl_xor_sync(0xFFFFFFFFu, acc, off);
    if (lane == 0) g_partial[rs * E_ + e] = acc;
}

// ---------------------------------------------------------------------------
// Kernel B: error[e] = Dis[e,511] - sum_rs g_partial[rs,e]  (computed
// redundantly per block from L2-cached partials), then
//   W[i] = W0[i] + LR * sum_e error[e] * Fx[rs,e,n]
// Also writes gam_vector into the output tail.
// ---------------------------------------------------------------------------
__global__ __launch_bounds__(256) void k_weights(
        const float* __restrict__ Fx,
        const float* __restrict__ Dis,
        const float* __restrict__ W0,
        float* __restrict__ gam_out) {
    __shared__ float sErr[E_];
    const int tid = threadIdx.x;

    if (tid < E_) {
        float s = 0.0f;
        #pragma unroll
        for (int rs = 0; rs < RS_; rs++) s += g_partial[rs * E_ + tid];
        sErr[tid] = Dis[tid * LEN_C + (LEN_C - 1)] - s;
    }
    __syncthreads();

    const int i = blockIdx.x * 256 + tid;
    const int rs = i >> 9;
    const int n  = i & (LEN_C - 1);
    float s = 0.0f;
    #pragma unroll
    for (int e = 0; e < E_; e++)
        s += sErr[e] * Fx[(rs * E_ + e) * LEN_C + n];
    g_W[i] = W0[i] + LRATE * s;

    if (i < LEN_C)
        gam_out[i] = powf(GAMMA_, (float)(LEN_C - 1 - i));
}

// ---------------------------------------------------------------------------
// Kernel C (the 1 GiB streamer), persistent-grid version:
//   out[t,e] = sum_{rs,n} Fx_extend[t,rs,e,n] * W[rs,n]
// Grid = 444 CTAs (3/SM x 148), each CTA stages the 64KB weight tile into
// dynamic smem ONCE, then grid-strides over t. Fxe read with __ldcs
// (evict-first) so g_W / partial sums stay L2-resident.
//
// Per t: flat float4 index v in [0, 32768): row = v/128 (rs*8+e), n4 = v%128.
// Thread tid, iteration it: v = it*512 + tid
//   row = it*4 + tid/128  -> e alternates e0 (even it) / e0+4 (odd it)
//   rs  = row>>3, n4 = tid&127 (fixed per thread)
// ---------------------------------------------------------------------------
extern __shared__ float4 sW[];      // 4096 float4 = 64KB

__global__ __launch_bounds__(512) void k_main(const float* __restrict__ Fxe,
                                              float* __restrict__ out) {
    const int tid = threadIdx.x;
    __shared__ float sAcc[E_];

    // Stage W into smem once (coalesced float4, L2-resident)
    const float4* W4 = reinterpret_cast<const float4*>(g_W);
    #pragma unroll
    for (int i = 0; i < 8; i++) sW[tid + i * 512] = W4[tid + i * 512];

    const int e0 = tid >> 7;     // 0..3
    const int n4 = tid & 127;
    const float4 w[16] = {       // pre-load this thread's 16 weight vectors? No:
        sW[0], sW[0], sW[0], sW[0], sW[0], sW[0], sW[0], sW[0],
        sW[0], sW[0], sW[0], sW[0], sW[0], sW[0], sW[0], sW[0]
    }; (void)w; // (placeholder removed below — weights read from smem per iter)

    for (int t = blockIdx.x; t < T_; t += gridDim.x) {
        if (tid < E_) sAcc[tid] = 0.0f;
        __syncthreads();

        const float4* X = reinterpret_cast<const float4*>(Fxe) + (size_t)t * 32768;

        float acc0 = 0.0f;           // e = e0      (even iterations)
        float acc1 = 0.0f;           // e = e0 + 4  (odd iterations)

        #pragma unroll 8
        for (int it = 0; it < 64; it++) {
            const int v   = it * 512 + tid;
            const int row = it * 4 + e0;
            const int rs  = row >> 3;
            const float4 x = __ldcs(&X[v]);
            const float4 ww = sW[rs * 128 + n4];
            const float d = x.x * ww.x + x.y * ww.y + x.z * ww.z + x.w * ww.w;
            if (it & 1) acc1 += d; else acc0 += d;
        }

        // Warp reduce (all lanes of a warp share e0)
        #pragma unroll
        for (int off = 16; off > 0; off >>= 1) {
            acc0 += __shfl_xor_sync(0xFFFFFFFFu, acc0, off);
            acc1 += __shfl_xor_sync(0xFFFFFFFFu, acc1, off);
        }
        if ((tid & 31) == 0) {
            atomicAdd(&sAcc[e0],     acc0);
            atomicAdd(&sAcc[e0 + 4], acc1);
        }
        __syncthreads();
        if (tid < E_) out[t * E_ + tid] = sAcc[tid];
        __syncthreads();   // protect sAcc re-zero on next iteration
    }
}

// ---------------------------------------------------------------------------
extern "C" void kernel_launch(void* const* d_in, const int* in_sizes, int n_in,
                              void* d_out, int out_size) {
    const float* Fx  = (const float*)d_in[0];   // [R,S,E,LEN_C]
    const float* Dis = (const float*)d_in[1];   // [E,LEN_C]
    const float* Fxe = (const float*)d_in[2];   // [T,R,S,E,LEN_C]
    const float* W0  = (const float*)d_in[3];   // [R,S,LEN_C]
    float* out = (float*)d_out;                 // [T*E] anti_noise ++ [LEN_C] gamma

    k_error_partial<<<RS_, 256>>>(Fx, W0);
    k_weights<<<W_ELEMS / 256, 256>>>(Fx, Dis, W0, out + (size_t)T_ * E_);

    static bool attr_set = false;
    if (!attr_set) {
        cudaFuncSetAttribute(k_main, cudaFuncAttributeMaxDynamicSharedMemorySize, 65536);
        attr_set = true;
    }
    k_main<<<444, 512, 65536>>>(Fxe, out);
}

// round 3
// speedup vs baseline: 1.0617x; 1.0287x over previous
#include <cuda_runtime.h>

// Problem constants (match reference)
#define LRATE  0.001f
#define GAMMA_ 0.99f
#define LEN_C  512
#define R_     4
#define S_     8
#define E_     8
#define T_     2048
#define RS_    (R_ * S_)            // 32
#define W_ELEMS (RS_ * LEN_C)       // 16384 floats = 64KB

#define PRO_BLOCKS 64               // <= SM count: all resident -> spin-safe

// Scratch (allocation-free rule: __device__ globals)
__device__ float    g_partial[RS_ * E_];   // per-(rs,e) partial dot products
__device__ float    g_W[W_ELEMS];          // updated control weights
__device__ unsigned g_barA = 0;            // grid barrier counters (self-reset)
__device__ unsigned g_barB = 0;

// ---------------------------------------------------------------------------
// Fused prologue (single kernel, software grid barrier):
//  Phase 1: g_partial[rs,e] = sum_n Fx[rs,e,n] * W0[rs,n]   (256 rows)
//  ---- grid barrier ----
//  Phase 2: err[e] = Dis[e,511] - sum_rs g_partial[rs,e]
//           g_W[i] = W0[i] + LR * sum_e err[e] * Fx[rs,e,n]
//           gam_out[i] = GAMMA^(511-i)   (i < 512)
// 64 blocks x 256 threads. Counters reset by last block for graph replays.
// ---------------------------------------------------------------------------
__global__ __launch_bounds__(256) void k_prologue(
        const float* __restrict__ Fx,
        const float* __restrict__ Dis,
        const float* __restrict__ W0,
        float* __restrict__ gam_out) {
    const int tid  = threadIdx.x;
    const int b    = blockIdx.x;
    const int wid  = tid >> 5;
    const int lane = tid & 31;

    // ---- Phase 1: 4 rows per block, 2 warps per row ----
    {
        const int row  = 4 * b + (wid >> 1);      // (rs<<3)|e
        const int half = wid & 1;
        const int rs   = row >> 3;
        const float4* Fx4 = reinterpret_cast<const float4*>(Fx) + row * 128;
        const float4* W4  = reinterpret_cast<const float4*>(W0) + rs  * 128;
        const int j = half * 64 + lane * 2;
        float4 x0 = Fx4[j],     w0 = W4[j];
        float4 x1 = Fx4[j + 1], w1 = W4[j + 1];
        float acc = x0.x * w0.x + x0.y * w0.y + x0.z * w0.z + x0.w * w0.w
                  + x1.x * w1.x + x1.y * w1.y + x1.z * w1.z + x1.w * w1.w;
        #pragma unroll
        for (int off = 16; off > 0; off >>= 1)
            acc += __shfl_xor_sync(0xFFFFFFFFu, acc, off);
        // two warps per row: combine via the half-partner using smem
        __shared__ float sHalf[8];                // one slot per warp
        if (lane == 0) sHalf[wid] = acc;
        __syncthreads();
        if (tid < 4)                               // one thread per row
            g_partial[4 * b + tid] = sHalf[2 * tid] + sHalf[2 * tid + 1];
    }

    // gamma vector: independent of everything — emit here (blocks 0,1)
    {
        const int i = b * 256 + tid;
        if (i < LEN_C) gam_out[i] = powf(GAMMA_, (float)(LEN_C - 1 - i));
    }

    // ---- Grid barrier (all PRO_BLOCKS resident by construction) ----
    __threadfence();
    __syncthreads();
    if (tid == 0) {
        atomicAdd(&g_barA, 1u);
        while (*((volatile unsigned*)&g_barA) < PRO_BLOCKS) { __nanosleep(64); }
    }
    __syncthreads();
    __threadfence();   // acquire: g_partial stores from all blocks now visible

    // ---- Phase 2 ----
    __shared__ float sErr[E_];
    if (tid < E_) {
        float s = 0.0f;
        #pragma unroll
        for (int rs = 0; rs < RS_; rs++) s += g_partial[(rs << 3) | tid];
        sErr[tid] = Dis[tid * LEN_C + (LEN_C - 1)] - s;
    }
    __syncthreads();

    const int i  = b * 256 + tid;          // 64*256 == W_ELEMS exactly
    const int rs = i >> 9;
    const int n  = i & (LEN_C - 1);
    float s = 0.0f;
    #pragma unroll
    for (int e = 0; e < E_; e++)
        s += sErr[e] * Fx[(rs * E_ + e) * LEN_C + n];
    g_W[i] = W0[i] + LRATE * s;

    // ---- reset barrier counters for the next graph replay ----
    __threadfence();
    __syncthreads();
    if (tid == 0) {
        unsigned v = atomicAdd(&g_barB, 1u);
        if (v == PRO_BLOCKS - 1) {         // last block: all adds to A and B done
            g_barA = 0;
            g_barB = 0;
            __threadfence();
        }
    }
}

// ---------------------------------------------------------------------------
// Kernel C (the 1 GiB streamer), persistent-grid:
//   out[t,e] = sum_{rs,n} Fx_extend[t,rs,e,n] * W[rs,n]
// Grid = 444 CTAs (3/SM x 148). Each CTA stages the 64KB weight tile into
// dynamic smem once, then grid-strides over t. Fxe read with __ldcs.
// Thread mapping per t: v = it*512 + tid, row = it*4 + tid/128,
//   e alternates e0/e0+4 on even/odd it; rs = row>>3; n4 = tid&127 fixed.
// ---------------------------------------------------------------------------
extern __shared__ float4 sW[];      // 4096 float4 = 64KB

__global__ __launch_bounds__(512) void k_main(const float* __restrict__ Fxe,
                                              float* __restrict__ out) {
    const int tid  = threadIdx.x;
    const int wid  = tid >> 5;      // 0..15
    const int lane = tid & 31;
    __shared__ float sRed[16][2];

    // Stage W into smem once (coalesced float4, L2-resident)
    const float4* W4 = reinterpret_cast<const float4*>(g_W);
    #pragma unroll
    for (int i = 0; i < 8; i++) sW[tid + i * 512] = W4[tid + i * 512];
    __syncthreads();

    const int e0 = tid >> 7;     // 0..3 (uniform per warp)
    const int n4 = tid & 127;

    for (int t = blockIdx.x; t < T_; t += gridDim.x) {
        const float4* X = reinterpret_cast<const float4*>(Fxe) + (size_t)t * 32768;

        float acc0 = 0.0f;           // e = e0      (even iterations)
        float acc1 = 0.0f;           // e = e0 + 4  (odd iterations)

        #pragma unroll 8
        for (int it = 0; it < 64; it++) {
            const int v   = it * 512 + tid;
            const int row = it * 4 + e0;
            const int rs  = row >> 3;
            const float4 x = __ldcs(&X[v]);
            const float4 w = sW[rs * 128 + n4];
            const float d = x.x * w.x + x.y * w.y + x.z * w.z + x.w * w.w;
            if (it & 1) acc1 += d; else acc0 += d;
        }

        #pragma unroll
        for (int off = 16; off > 0; off >>= 1) {
            acc0 += __shfl_xor_sync(0xFFFFFFFFu, acc0, off);
            acc1 += __shfl_xor_sync(0xFFFFFFFFu, acc1, off);
        }
        if (lane == 0) { sRed[wid][0] = acc0; sRed[wid][1] = acc1; }
        __syncthreads();
        if (tid < E_) {
            const int e   = tid;
            const int grp = e & 3;       // which e0 group
            const int sel = e >> 2;      // acc0 or acc1
            out[t * E_ + e] = sRed[grp * 4 + 0][sel] + sRed[grp * 4 + 1][sel]
                            + sRed[grp * 4 + 2][sel] + sRed[grp * 4 + 3][sel];
        }
        __syncthreads();   // protect sRed reuse next t
    }
}

// ---------------------------------------------------------------------------
extern "C" void kernel_launch(void* const* d_in, const int* in_sizes, int n_in,
                              void* d_out, int out_size) {
    const float* Fx  = (const float*)d_in[0];   // [R,S,E,LEN_C]
    const float* Dis = (const float*)d_in[1];   // [E,LEN_C]
    const float* Fxe = (const float*)d_in[2];   // [T,R,S,E,LEN_C]
    const float* W0  = (const float*)d_in[3];   // [R,S,LEN_C]
    float* out = (float*)d_out;                 // [T*E] anti_noise ++ [LEN_C] gamma

    k_prologue<<<PRO_BLOCKS, 256>>>(Fx, Dis, W0, out + (size_t)T_ * E_);

    static bool attr_set = false;
    if (!attr_set) {
        cudaFuncSetAttribute(k_main, cudaFuncAttributeMaxDynamicSharedMemorySize, 65536);
        attr_set = true;
    }
    k_main<<<444, 512, 65536>>>(Fxe, out);
}

// round 4
// speedup vs baseline: 1.0922x; 1.0287x over previous
#include <cuda_runtime.h>

// Problem constants (match reference)
#define LRATE  0.001f
#define GAMMA_ 0.99f
#define LEN_C  512
#define E_     8
#define T_     2048
#define RS_    32
#define W_ELEMS 16384               // RS_ * LEN_C floats = 64KB

#define GRID_  444                  // 3 CTAs/SM x 148 SMs: all co-resident
#define PRO_   64                   // blocks participating in prologue phase 1

// Scratch (allocation-free rule: __device__ globals)
__device__ float    g_partial[RS_ * E_];
__device__ float    g_W[W_ELEMS];
__device__ unsigned g_bar1   = 0;   // 64-block prologue barrier
__device__ unsigned g_bar2   = 0;   // 444-block grid barrier
__device__ unsigned g_ticket = 0;   // dynamic t dispenser
__device__ unsigned g_done   = 0;   // completion counter -> resets all

extern __shared__ float4 sW[];      // 4096 float4 = 64KB weight tile

__device__ __forceinline__ void spin_until(unsigned* ctr, unsigned target) {
    while (*((volatile unsigned*)ctr) < target) __nanosleep(64);
}

// ---------------------------------------------------------------------------
// One fused persistent kernel.
//   Prologue (blocks 0..63):  g_partial[row] = <Fx[row,:], W0[rs,:]>
//   64-barrier; blocks 0..31: err[e] = Dis[e,511]-sum; g_W = W0 + LR*err.Fx
//   444-barrier; all blocks:  stage W->smem, ticket-loop over t:
//       out[t,e] = sum_{rs,n} Fxe[t,rs,e,n] * W[rs,n]
// Every block L2-prefetches its first 512KB chunk BEFORE the barriers so
// DRAM streams during the prologue.
// ---------------------------------------------------------------------------
__global__ __launch_bounds__(512, 3) void k_fused(
        const float* __restrict__ Fx,      // [RS_,E_,LEN_C]
        const float* __restrict__ Dis,     // [E_,LEN_C]
        const float* __restrict__ Fxe,     // [T_,RS_,E_,LEN_C]
        const float* __restrict__ W0,      // [RS_,LEN_C]
        float* __restrict__ out,           // [T_*E_]
        float* __restrict__ gam_out)       // [LEN_C]
{
    const int tid  = threadIdx.x;
    const int b    = blockIdx.x;
    const int wid  = tid >> 5;
    const int lane = tid & 31;

    __shared__ float    sH[16];
    __shared__ float    sErr[E_];
    __shared__ float    sRed[16][2];
    __shared__ unsigned sT;

    // ---- grab first t, prefetch its whole 512KB chunk into L2 ----
    if (tid == 0) sT = atomicAdd(&g_ticket, 1u);
    __syncthreads();
    const unsigned t0 = sT;               // 0..443, always < T_
    {
        const char* base = (const char*)Fxe + (size_t)t0 * 524288;
        #pragma unroll
        for (int k = 0; k < 8; k++)
            asm volatile("prefetch.global.L2 [%0];"
                         :: "l"(base + (size_t)(k * 512 + tid) * 128));
    }

    // ---- gamma vector (block 0, independent of everything) ----
    if (b == 0)
        gam_out[tid] = powf(GAMMA_, (float)(LEN_C - 1 - tid));

    // ---- prologue ----
    if (b < PRO_) {
        // Phase 1: 4 rows/block, 4 warps/row (row = rs*8+e)
        const int row = 4 * b + (wid >> 2);
        const int rs  = row >> 3;
        const int j   = (wid & 3) * 32 + lane;        // float4 index 0..127
        const float4 x = reinterpret_cast<const float4*>(Fx)[row * 128 + j];
        const float4 w = reinterpret_cast<const float4*>(W0)[rs  * 128 + j];
        float acc = x.x * w.x + x.y * w.y + x.z * w.z + x.w * w.w;
        #pragma unroll
        for (int off = 16; off > 0; off >>= 1)
            acc += __shfl_xor_sync(0xFFFFFFFFu, acc, off);
        if (lane == 0) sH[wid] = acc;
        __syncthreads();
        if (tid < 4)
            g_partial[4 * b + tid] =
                sH[4 * tid] + sH[4 * tid + 1] + sH[4 * tid + 2] + sH[4 * tid + 3];

        // 64-block barrier
        __threadfence();
        __syncthreads();
        if (tid == 0) { atomicAdd(&g_bar1, 1u); spin_until(&g_bar1, PRO_); }
        __syncthreads();
        __threadfence();

        // Phase 2 (blocks 0..31): error + weight update
        if (b < 32) {
            if (tid < E_) {
                float s = 0.0f;
                #pragma unroll
                for (int r = 0; r < RS_; r++) s += g_partial[(r << 3) | tid];
                sErr[tid] = Dis[tid * LEN_C + (LEN_C - 1)] - s;
            }
            __syncthreads();
            const int i  = b * 512 + tid;             // covers [0, 16384)
            const int rs2 = i >> 9;
            const int n   = i & (LEN_C - 1);
            float s = 0.0f;
            #pragma unroll
            for (int e = 0; e < E_; e++)
                s += sErr[e] * Fx[(rs2 * E_ + e) * LEN_C + n];
            g_W[i] = W0[i] + LRATE * s;
        }
    }

    // ---- full grid barrier (all 444 resident by construction) ----
    __threadfence();
    __syncthreads();
    if (tid == 0) { atomicAdd(&g_bar2, 1u); spin_until(&g_bar2, GRID_); }
    __syncthreads();
    __threadfence();          // acquire: g_W stores now visible

    // ---- stage weights into smem ----
    const float4* W4 = reinterpret_cast<const float4*>(g_W);
    #pragma unroll
    for (int i = 0; i < 8; i++) sW[tid + i * 512] = W4[tid + i * 512];
    __syncthreads();

    // ---- main streaming loop (dynamic tickets) ----
    // Per t: v = it*512+tid, row = it*4+e0, e alternates e0/e0+4 per it,
    // rs = row>>3, n4 = tid&127 fixed per thread.
    const int e0 = tid >> 7;
    const int n4 = tid & 127;
    unsigned t = t0;

    while (t < T_) {
        const float4* X = reinterpret_cast<const float4*>(Fxe) + (size_t)t * 32768;

        float acc0 = 0.0f;            // e = e0      (even it)
        float acc1 = 0.0f;            // e = e0 + 4  (odd it)

        #pragma unroll 8
        for (int it = 0; it < 64; it++) {
            const int v   = it * 512 + tid;
            const int row = it * 4 + e0;
            const int rs  = row >> 3;
            const float4 x = __ldcs(&X[v]);
            const float4 w = sW[rs * 128 + n4];
            const float d = x.x * w.x + x.y * w.y + x.z * w.z + x.w * w.w;
            if (it & 1) acc1 += d; else acc0 += d;
        }

        #pragma unroll
        for (int off = 16; off > 0; off >>= 1) {
            acc0 += __shfl_xor_sync(0xFFFFFFFFu, acc0, off);
            acc1 += __shfl_xor_sync(0xFFFFFFFFu, acc1, off);
        }
        if (lane == 0) { sRed[wid][0] = acc0; sRed[wid][1] = acc1; }
        __syncthreads();
        if (tid < E_) {
            const int grp = tid & 3;
            const int sel = tid >> 2;
            out[t * E_ + tid] = sRed[grp * 4 + 0][sel] + sRed[grp * 4 + 1][sel]
                              + sRed[grp * 4 + 2][sel] + sRed[grp * 4 + 3][sel];
        }
        if (tid == 0) sT = atomicAdd(&g_ticket, 1u);
        __syncthreads();              // sT ready; sRed consumed
        t = sT;
    }

    // ---- reset counters for next graph replay (444th finisher) ----
    __syncthreads();
    if (tid == 0) {
        const unsigned v = atomicAdd(&g_done, 1u);
        if (v == GRID_ - 1) {
            g_ticket = 0; g_bar1 = 0; g_bar2 = 0; g_done = 0;
            __threadfence();
        }
    }
}

// ---------------------------------------------------------------------------
extern "C" void kernel_launch(void* const* d_in, const int* in_sizes, int n_in,
                              void* d_out, int out_size) {
    const float* Fx  = (const float*)d_in[0];   // [R,S,E,LEN_C]
    const float* Dis = (const float*)d_in[1];   // [E,LEN_C]
    const float* Fxe = (const float*)d_in[2];   // [T,R,S,E,LEN_C]
    const float* W0  = (const float*)d_in[3];   // [R,S,LEN_C]
    float* out = (float*)d_out;                 // [T*E] anti_noise ++ [LEN_C] gamma

    static bool attr_set = false;
    if (!attr_set) {
        cudaFuncSetAttribute(k_fused, cudaFuncAttributeMaxDynamicSharedMemorySize, 65536);
        attr_set = true;
    }
    k_fused<<<GRID_, 512, 65536>>>(Fx, Dis, Fxe, W0, out, out + (size_t)T_ * E_);
}